// round 7
// baseline (speedup 1.0000x reference)
#include <cuda_runtime.h>
#include <math.h>

constexpr int N_   = 50000;
constexpr int E_   = 400000;
constexpr int ETOT = E_ + N_;   // edges + self loops

// ---------------- scratch ---------------------------------------------------
__device__ __align__(16) float g_h1[N_ * 256];   // layer1 features [N,4,64]
__device__ __align__(16) float g_asrc1[N_ * 4];
__device__ __align__(16) float g_adst1[N_ * 4];
__device__ __align__(16) float g_x2[N_ * 64];    // layer1 out / layer2 in
__device__ __align__(16) float g_h2[N_ * 64];
__device__ float g_asrc2[N_];
__device__ float g_adst2[N_];
__device__ float g_vs1[16 * 4];
__device__ float g_vd1[16 * 4];
__device__ float g_vs2[64];
__device__ float g_vd2[64];
__device__ int   g_deg[N_];
__device__ int   g_rp[N_ + 1];
__device__ int   g_cursor[N_];
__device__ int   g_csr_src[ETOT];
__device__ int   g_is64;

// ---------------- helpers ---------------------------------------------------
__device__ __forceinline__ float lrelu(float x) { return x > 0.f ? x : 0.2f * x; }
__device__ __forceinline__ float eluf(float x)  { return x > 0.f ? x : expm1f(x); }

__device__ __forceinline__ int2 load_edge(const void* ei, int e) {
    int2 r;
    if (g_is64) {
        const long long* p = (const long long*)ei;
        r.x = (int)p[e]; r.y = (int)p[E_ + e];
    } else {
        const int* p = (const int*)ei;
        r.x = p[e]; r.y = p[E_ + e];
    }
    return r;
}

// ---------------- setup: detect dtype, init degrees, logit vectors ---------
__global__ void k_setup(const unsigned int* __restrict__ ei,
                        const float* __restrict__ W1,
                        const float* __restrict__ as1, const float* __restrict__ ad1,
                        const float* __restrict__ W2,
                        const float* __restrict__ as2, const float* __restrict__ ad2) {
    int i = blockIdx.x * blockDim.x + threadIdx.x;
    if (i < N_) g_deg[i] = 1;                      // self loop
    if (blockIdx.x == 0) {
        int t = threadIdx.x;
        if (t == 0) {
            int ok = 1;
            for (int k = 0; k < 32; k++)
                if (ei[2 * k + 1] != 0u) { ok = 0; break; }
            g_is64 = ok;
        }
        if (t < 64) {           // v1[k][h] = sum_c W1[k,h*64+c] * att1[h,c]
            int k = t >> 2, h = t & 3;
            float s = 0.f, d = 0.f;
            for (int c = 0; c < 64; c++) {
                float w = W1[k * 256 + h * 64 + c];
                s = fmaf(w, as1[h * 64 + c], s);
                d = fmaf(w, ad1[h * 64 + c], d);
            }
            g_vs1[k * 4 + h] = s;
            g_vd1[k * 4 + h] = d;
        }
        if (t >= 64 && t < 128) {   // v2[k] = sum_c W2[k,c] * att2[c]
            int k = t - 64;
            float s = 0.f, d = 0.f;
            for (int c = 0; c < 64; c++) {
                float w = W2[k * 64 + c];
                s = fmaf(w, as2[c], s);
                d = fmaf(w, ad2[c], d);
            }
            g_vs2[k] = s;
            g_vd2[k] = d;
        }
    }
}

__global__ void k_hist(const void* __restrict__ ei) {
    int e = blockIdx.x * blockDim.x + threadIdx.x;
    if (e >= E_) return;
    int2 sd = load_edge(ei, e);
    atomicAdd(&g_deg[sd.y], 1);
}

// ---------------- single-kernel exclusive scan (1 block, reduce-then-scan) --
__global__ void k_scan_all() {
    constexpr int CH = (N_ + 1023) / 1024;    // 49 contiguous elems per thread
    __shared__ int swarp[32];
    int t = threadIdx.x;
    int lane = t & 31, wid = t >> 5;
    int beg = t * CH;
    int end = min(beg + CH, N_);
    int sum = 0;
    for (int i = beg; i < end; i++) sum += g_deg[i];
    int x = sum;
    #pragma unroll
    for (int o = 1; o < 32; o <<= 1) {
        int y = __shfl_up_sync(0xffffffffu, x, o);
        if (lane >= o) x += y;
    }
    if (lane == 31) swarp[wid] = x;
    __syncthreads();
    if (wid == 0) {
        int y = swarp[lane];
        #pragma unroll
        for (int o = 1; o < 32; o <<= 1) {
            int z = __shfl_up_sync(0xffffffffu, y, o);
            if (lane >= o) y += z;
        }
        swarp[lane] = y;
    }
    __syncthreads();
    int run = ((wid > 0) ? swarp[wid - 1] : 0) + x - sum;   // exclusive prefix
    for (int i = beg; i < end; i++) {
        int dv = g_deg[i];
        g_rp[i] = run;
        g_cursor[i] = run;
        run += dv;
    }
    if (t == 0) g_rp[N_] = swarp[31];
}

__global__ void k_scatter(const void* __restrict__ ei) {
    int e = blockIdx.x * blockDim.x + threadIdx.x;
    if (e >= ETOT) return;
    int s, d;
    if (e < E_) { int2 sd = load_edge(ei, e); s = sd.x; d = sd.y; }
    else        { s = d = e - E_; }
    int pos = atomicAdd(&g_cursor[d], 1);
    g_csr_src[pos] = s;
}

// ---------------- layer 1 GEMM + logits ------------------------------------
// h1 = x @ W1 ; asrc1/adst1 = x @ v1 (fused, threads 0-127)
__global__ void k_gemm1(const float* __restrict__ x, const float* __restrict__ W) {
    __shared__ float Ws[16 * 256];
    __shared__ float xs[16 * 16];
    __shared__ float vs[64], vd[64];
    int t = threadIdx.x;
    for (int i = t; i < 4096; i += 256) Ws[i] = W[i];
    if (t < 64)  vs[t] = g_vs1[t];
    else if (t < 128) vd[t - 64] = g_vd1[t - 64];
    int nb = blockIdx.x * 16;
    {
        int n = nb + (t >> 4);
        xs[t] = (n < N_) ? x[n * 16 + (t & 15)] : 0.f;
    }
    __syncthreads();
    if (t < 128) {                        // fused attention logits
        int i = t >> 3;                   // node in tile
        int j = t & 7;                    // 0-3 src heads, 4-7 dst heads
        int h = j & 3;
        const float* v = (j < 4) ? vs : vd;
        float acc = 0.f;
        #pragma unroll
        for (int k = 0; k < 16; k++) acc = fmaf(xs[i * 16 + k], v[k * 4 + h], acc);
        int n = nb + i;
        if (n < N_) {
            if (j < 4) g_asrc1[n * 4 + h] = acc;
            else       g_adst1[n * 4 + h] = acc;
        }
    }
    #pragma unroll 4
    for (int i = 0; i < 16; i++) {
        int n = nb + i;
        if (n >= N_) break;
        float acc = 0.f;
        #pragma unroll
        for (int k = 0; k < 16; k++) acc = fmaf(xs[i * 16 + k], Ws[k * 256 + t], acc);
        g_h1[n * 256 + t] = acc;
    }
}

// ---------------- layer 2 GEMM: h2 = x2 @ W2 -------------------------------
__global__ void k_gemm2(const float* __restrict__ W) {
    __shared__ float Ws[64 * 64];
    __shared__ float xs[16 * 65];
    int t = threadIdx.x;
    int col = t & 63;
    int g = t >> 6;
    for (int i = t; i < 4096; i += 256) Ws[i] = W[i];
    int nb = blockIdx.x * 16;
    for (int i = t; i < 1024; i += 256) {
        int n = nb + (i >> 6);
        xs[(i >> 6) * 65 + (i & 63)] = (n < N_) ? g_x2[n * 64 + (i & 63)] : 0.f;
    }
    __syncthreads();
    for (int it = 0; it < 4; it++) {
        int i = it * 4 + g;
        int n = nb + i;
        float acc = 0.f;
        #pragma unroll
        for (int k = 0; k < 64; k++) acc = fmaf(xs[i * 65 + k], Ws[k * 64 + col], acc);
        if (n < N_) g_h2[n * 64 + col] = acc;
    }
}

// ---------------- layer 1 fused softmax-aggregate (warp per dst) -----------
// No max-subtraction: logits are O(1) so exp() is exact-safe in fp32.
// Also emits layer-2 attention logits from the produced x2 row.
__global__ void k_agg1(const float* __restrict__ b1) {
    __shared__ int    sm_s[8 * 32];
    __shared__ float4 sm_ex[8 * 32];
    int lane = threadIdx.x & 31;
    int w = threadIdx.x >> 5;
    int d = blockIdx.x * 8 + w;
    if (d >= N_) return;
    int rsb = g_rp[d];
    int deg = g_rp[d + 1] - rsb;
    float4 adst = *(const float4*)&g_adst1[d * 4];
    int head = lane >> 3;

    float4 den = make_float4(0.f, 0.f, 0.f, 0.f);
    float4 a0 = make_float4(0.f, 0.f, 0.f, 0.f);
    float4 a1 = make_float4(0.f, 0.f, 0.f, 0.f);

    if (deg <= 32) {
        int s = -1;
        float4 ex = make_float4(0.f, 0.f, 0.f, 0.f);
        if (lane < deg) {
            s = g_csr_src[rsb + lane];
            float4 a = *(const float4*)&g_asrc1[s * 4];
            ex = make_float4(__expf(lrelu(a.x + adst.x)), __expf(lrelu(a.y + adst.y)),
                             __expf(lrelu(a.z + adst.z)), __expf(lrelu(a.w + adst.w)));
            den = ex;
        }
        sm_s[w * 32 + lane] = s;
        sm_ex[w * 32 + lane] = ex;
        __syncwarp();
        const float* exb = (const float*)&sm_ex[w * 32];
        int j = 0;
        for (; j + 3 < deg; j += 4) {
            int sj0 = sm_s[w * 32 + j],     sj1 = sm_s[w * 32 + j + 1];
            int sj2 = sm_s[w * 32 + j + 2], sj3 = sm_s[w * 32 + j + 3];
            float e0 = exb[j * 4 + head],       e1 = exb[(j + 1) * 4 + head];
            float e2 = exb[(j + 2) * 4 + head], e3 = exb[(j + 3) * 4 + head];
            const float4* p0 = (const float4*)&g_h1[sj0 * 256 + lane * 8];
            const float4* p1 = (const float4*)&g_h1[sj1 * 256 + lane * 8];
            const float4* p2 = (const float4*)&g_h1[sj2 * 256 + lane * 8];
            const float4* p3 = (const float4*)&g_h1[sj3 * 256 + lane * 8];
            float4 u00 = p0[0], u01 = p0[1];
            float4 u10 = p1[0], u11 = p1[1];
            float4 u20 = p2[0], u21 = p2[1];
            float4 u30 = p3[0], u31 = p3[1];
            a0.x = fmaf(e0, u00.x, a0.x); a0.y = fmaf(e0, u00.y, a0.y);
            a0.z = fmaf(e0, u00.z, a0.z); a0.w = fmaf(e0, u00.w, a0.w);
            a1.x = fmaf(e0, u01.x, a1.x); a1.y = fmaf(e0, u01.y, a1.y);
            a1.z = fmaf(e0, u01.z, a1.z); a1.w = fmaf(e0, u01.w, a1.w);
            a0.x = fmaf(e1, u10.x, a0.x); a0.y = fmaf(e1, u10.y, a0.y);
            a0.z = fmaf(e1, u10.z, a0.z); a0.w = fmaf(e1, u10.w, a0.w);
            a1.x = fmaf(e1, u11.x, a1.x); a1.y = fmaf(e1, u11.y, a1.y);
            a1.z = fmaf(e1, u11.z, a1.z); a1.w = fmaf(e1, u11.w, a1.w);
            a0.x = fmaf(e2, u20.x, a0.x); a0.y = fmaf(e2, u20.y, a0.y);
            a0.z = fmaf(e2, u20.z, a0.z); a0.w = fmaf(e2, u20.w, a0.w);
            a1.x = fmaf(e2, u21.x, a1.x); a1.y = fmaf(e2, u21.y, a1.y);
            a1.z = fmaf(e2, u21.z, a1.z); a1.w = fmaf(e2, u21.w, a1.w);
            a0.x = fmaf(e3, u30.x, a0.x); a0.y = fmaf(e3, u30.y, a0.y);
            a0.z = fmaf(e3, u30.z, a0.z); a0.w = fmaf(e3, u30.w, a0.w);
            a1.x = fmaf(e3, u31.x, a1.x); a1.y = fmaf(e3, u31.y, a1.y);
            a1.z = fmaf(e3, u31.z, a1.z); a1.w = fmaf(e3, u31.w, a1.w);
        }
        for (; j < deg; j++) {
            int sj = sm_s[w * 32 + j];
            float e0 = exb[j * 4 + head];
            const float4* p0 = (const float4*)&g_h1[sj * 256 + lane * 8];
            float4 u0 = p0[0], u1 = p0[1];
            a0.x = fmaf(e0, u0.x, a0.x); a0.y = fmaf(e0, u0.y, a0.y);
            a0.z = fmaf(e0, u0.z, a0.z); a0.w = fmaf(e0, u0.w, a0.w);
            a1.x = fmaf(e0, u1.x, a1.x); a1.y = fmaf(e0, u1.y, a1.y);
            a1.z = fmaf(e0, u1.z, a1.z); a1.w = fmaf(e0, u1.w, a1.w);
        }
    } else {
        // generic path: single pass (no max needed)
        for (int base = 0; base < deg; base += 32) {
            int i = base + lane;
            int s = -1;
            float4 ex = make_float4(0.f, 0.f, 0.f, 0.f);
            if (i < deg) {
                s = g_csr_src[rsb + i];
                float4 a = *(const float4*)&g_asrc1[s * 4];
                ex.x = __expf(lrelu(a.x + adst.x));
                ex.y = __expf(lrelu(a.y + adst.y));
                ex.z = __expf(lrelu(a.z + adst.z));
                ex.w = __expf(lrelu(a.w + adst.w));
                den.x += ex.x; den.y += ex.y; den.z += ex.z; den.w += ex.w;
            }
            sm_s[w * 32 + lane] = s;
            sm_ex[w * 32 + lane] = ex;
            __syncwarp();
            int cnt = min(32, deg - base);
            const float* exb = (const float*)&sm_ex[w * 32];
            for (int j = 0; j < cnt; j++) {
                int sj = sm_s[w * 32 + j];
                float exj = exb[j * 4 + head];
                const float4* hp = (const float4*)&g_h1[sj * 256 + lane * 8];
                float4 v0 = hp[0], v1 = hp[1];
                a0.x = fmaf(exj, v0.x, a0.x); a0.y = fmaf(exj, v0.y, a0.y);
                a0.z = fmaf(exj, v0.z, a0.z); a0.w = fmaf(exj, v0.w, a0.w);
                a1.x = fmaf(exj, v1.x, a1.x); a1.y = fmaf(exj, v1.y, a1.y);
                a1.z = fmaf(exj, v1.z, a1.z); a1.w = fmaf(exj, v1.w, a1.w);
            }
            __syncwarp();
        }
    }

    #pragma unroll
    for (int o = 16; o > 0; o >>= 1) {
        den.x += __shfl_xor_sync(0xffffffffu, den.x, o);
        den.y += __shfl_xor_sync(0xffffffffu, den.y, o);
        den.z += __shfl_xor_sync(0xffffffffu, den.z, o);
        den.w += __shfl_xor_sync(0xffffffffu, den.w, o);
    }
    float dh = (head == 0 ? den.x : head == 1 ? den.y : head == 2 ? den.z : den.w);
    float inv = 1.f / (dh + 1e-16f);
    a0.x *= inv; a0.y *= inv; a0.z *= inv; a0.w *= inv;
    a1.x *= inv; a1.y *= inv; a1.z *= inv; a1.w *= inv;
    #pragma unroll
    for (int o = 8; o <= 16; o <<= 1) {
        a0.x += __shfl_xor_sync(0xffffffffu, a0.x, o);
        a0.y += __shfl_xor_sync(0xffffffffu, a0.y, o);
        a0.z += __shfl_xor_sync(0xffffffffu, a0.z, o);
        a0.w += __shfl_xor_sync(0xffffffffu, a0.w, o);
        a1.x += __shfl_xor_sync(0xffffffffu, a1.x, o);
        a1.y += __shfl_xor_sync(0xffffffffu, a1.y, o);
        a1.z += __shfl_xor_sync(0xffffffffu, a1.z, o);
        a1.w += __shfl_xor_sync(0xffffffffu, a1.w, o);
    }
    if (lane < 8) {
        int c = lane * 8;
        float o0 = eluf(0.25f * a0.x + b1[c + 0]);
        float o1 = eluf(0.25f * a0.y + b1[c + 1]);
        float o2 = eluf(0.25f * a0.z + b1[c + 2]);
        float o3 = eluf(0.25f * a0.w + b1[c + 3]);
        float o4 = eluf(0.25f * a1.x + b1[c + 4]);
        float o5 = eluf(0.25f * a1.y + b1[c + 5]);
        float o6 = eluf(0.25f * a1.z + b1[c + 6]);
        float o7 = eluf(0.25f * a1.w + b1[c + 7]);
        float* op = &g_x2[d * 64 + c];
        op[0] = o0; op[1] = o1; op[2] = o2; op[3] = o3;
        op[4] = o4; op[5] = o5; op[6] = o6; op[7] = o7;
        float ps = o0 * g_vs2[c + 0] + o1 * g_vs2[c + 1] + o2 * g_vs2[c + 2] + o3 * g_vs2[c + 3]
                 + o4 * g_vs2[c + 4] + o5 * g_vs2[c + 5] + o6 * g_vs2[c + 6] + o7 * g_vs2[c + 7];
        float pd = o0 * g_vd2[c + 0] + o1 * g_vd2[c + 1] + o2 * g_vd2[c + 2] + o3 * g_vd2[c + 3]
                 + o4 * g_vd2[c + 4] + o5 * g_vd2[c + 5] + o6 * g_vd2[c + 6] + o7 * g_vd2[c + 7];
        #pragma unroll
        for (int o = 4; o > 0; o >>= 1) {
            ps += __shfl_xor_sync(0x000000ffu, ps, o);
            pd += __shfl_xor_sync(0x000000ffu, pd, o);
        }
        if (lane == 0) { g_asrc2[d] = ps; g_adst2[d] = pd; }
    }
}

// ---------------- layer 2 fused softmax-aggregate (warp per dst) -----------
__global__ void k_agg2(const float* __restrict__ b2, float* __restrict__ out) {
    __shared__ int   sm_s[8 * 32];
    __shared__ float sm_ex[8 * 32];
    int lane = threadIdx.x & 31;
    int w = threadIdx.x >> 5;
    int d = blockIdx.x * 8 + w;
    if (d >= N_) return;
    int rsb = g_rp[d];
    int deg = g_rp[d + 1] - rsb;
    float adst = g_adst2[d];

    float den = 0.f;
    float2 acc = make_float2(0.f, 0.f);

    if (deg <= 32) {
        int s = -1;
        float ex = 0.f;
        if (lane < deg) {
            s = g_csr_src[rsb + lane];
            ex = __expf(lrelu(g_asrc2[s] + adst));
            den = ex;
        }
        sm_s[w * 32 + lane] = s;
        sm_ex[w * 32 + lane] = ex;
        __syncwarp();
        int j = 0;
        for (; j + 3 < deg; j += 4) {
            int sj0 = sm_s[w * 32 + j],     sj1 = sm_s[w * 32 + j + 1];
            int sj2 = sm_s[w * 32 + j + 2], sj3 = sm_s[w * 32 + j + 3];
            float e0 = sm_ex[w * 32 + j],     e1 = sm_ex[w * 32 + j + 1];
            float e2 = sm_ex[w * 32 + j + 2], e3 = sm_ex[w * 32 + j + 3];
            float2 u0 = *(const float2*)&g_h2[sj0 * 64 + lane * 2];
            float2 u1 = *(const float2*)&g_h2[sj1 * 64 + lane * 2];
            float2 u2 = *(const float2*)&g_h2[sj2 * 64 + lane * 2];
            float2 u3 = *(const float2*)&g_h2[sj3 * 64 + lane * 2];
            acc.x = fmaf(e0, u0.x, acc.x); acc.y = fmaf(e0, u0.y, acc.y);
            acc.x = fmaf(e1, u1.x, acc.x); acc.y = fmaf(e1, u1.y, acc.y);
            acc.x = fmaf(e2, u2.x, acc.x); acc.y = fmaf(e2, u2.y, acc.y);
            acc.x = fmaf(e3, u3.x, acc.x); acc.y = fmaf(e3, u3.y, acc.y);
        }
        for (; j < deg; j++) {
            int sj = sm_s[w * 32 + j];
            float e0 = sm_ex[w * 32 + j];
            float2 u = *(const float2*)&g_h2[sj * 64 + lane * 2];
            acc.x = fmaf(e0, u.x, acc.x); acc.y = fmaf(e0, u.y, acc.y);
        }
    } else {
        for (int base = 0; base < deg; base += 32) {
            int i = base + lane;
            int s = -1;
            float ex = 0.f;
            if (i < deg) {
                s = g_csr_src[rsb + i];
                ex = __expf(lrelu(g_asrc2[s] + adst));
                den += ex;
            }
            sm_s[w * 32 + lane] = s;
            sm_ex[w * 32 + lane] = ex;
            __syncwarp();
            int cnt = min(32, deg - base);
            for (int j = 0; j < cnt; j++) {
                int sj = sm_s[w * 32 + j];
                float exj = sm_ex[w * 32 + j];
                float2 v = *(const float2*)&g_h2[sj * 64 + lane * 2];
                acc.x = fmaf(exj, v.x, acc.x);
                acc.y = fmaf(exj, v.y, acc.y);
            }
            __syncwarp();
        }
    }
    #pragma unroll
    for (int o = 16; o > 0; o >>= 1)
        den += __shfl_xor_sync(0xffffffffu, den, o);
    float inv = 1.f / (den + 1e-16f);
    int c = lane * 2;
    out[d * 64 + c + 0] = eluf(acc.x * inv + b2[c + 0]);
    out[d * 64 + c + 1] = eluf(acc.y * inv + b2[c + 1]);
}

// ---------------- launch ----------------------------------------------------
extern "C" void kernel_launch(void* const* d_in, const int* in_sizes, int n_in,
                              void* d_out, int out_size) {
    const float* x   = (const float*)d_in[0];
    const void*  ei  = d_in[1];
    const float* W1  = (const float*)d_in[2];
    const float* as1 = (const float*)d_in[3];
    const float* ad1 = (const float*)d_in[4];
    const float* b1  = (const float*)d_in[5];
    const float* W2  = (const float*)d_in[6];
    const float* as2 = (const float*)d_in[7];
    const float* ad2 = (const float*)d_in[8];
    const float* b2  = (const float*)d_in[9];
    float* out = (float*)d_out;

    k_setup<<<(N_ + 255) / 256, 256>>>((const unsigned int*)ei, W1, as1, ad1, W2, as2, ad2);
    k_hist<<<(E_ + 255) / 256, 256>>>(ei);
    k_scan_all<<<1, 1024>>>();
    k_scatter<<<(ETOT + 255) / 256, 256>>>(ei);

    k_gemm1<<<(N_ + 15) / 16, 256>>>(x, W1);
    k_agg1<<<(N_ + 7) / 8, 256>>>(b1);

    k_gemm2<<<(N_ + 15) / 16, 256>>>(W2);
    k_agg2<<<(N_ + 7) / 8, 256>>>(b2, out);
}

// round 8
// speedup vs baseline: 1.3665x; 1.3665x over previous
#include <cuda_runtime.h>
#include <math.h>

constexpr int N_   = 50000;
constexpr int E_   = 400000;
constexpr int ETOT = E_ + N_;   // edges + self loops
constexpr int SCAN_BLK = 1024;
constexpr int SCAN_NB  = (N_ + SCAN_BLK - 1) / SCAN_BLK;   // 49

// ---------------- scratch ---------------------------------------------------
__device__ __align__(16) float g_h1[N_ * 256];   // layer1 features [N,4,64]
__device__ __align__(16) float g_asrc1[N_ * 4];
__device__ __align__(16) float g_adst1[N_ * 4];
__device__ __align__(16) float g_x2[N_ * 64];    // layer1 out / layer2 in
__device__ __align__(16) float g_h2[N_ * 64];
__device__ float g_asrc2[N_];
__device__ float g_adst2[N_];
__device__ float g_vs1[16 * 4];
__device__ float g_vd1[16 * 4];
__device__ float g_vs2[64];
__device__ float g_vd2[64];
__device__ int   g_deg[N_];
__device__ int   g_rp[N_ + 1];
__device__ int   g_cursor[N_];
__device__ int   g_csr_src[ETOT];
__device__ int   g_bsum[SCAN_NB];
__device__ int   g_boff[SCAN_NB + 1];
__device__ int   g_is64;

// ---------------- helpers ---------------------------------------------------
__device__ __forceinline__ float lrelu(float x) { return x > 0.f ? x : 0.2f * x; }
__device__ __forceinline__ float eluf(float x)  { return x > 0.f ? x : expm1f(x); }

__device__ __forceinline__ int2 load_edge(const void* ei, int e) {
    int2 r;
    if (g_is64) {
        const long long* p = (const long long*)ei;
        r.x = (int)p[e]; r.y = (int)p[E_ + e];
    } else {
        const int* p = (const int*)ei;
        r.x = p[e]; r.y = p[E_ + e];
    }
    return r;
}

// ---------------- setup: detect dtype, init degrees, logit vectors ---------
__global__ void k_setup(const unsigned int* __restrict__ ei,
                        const float* __restrict__ W1,
                        const float* __restrict__ as1, const float* __restrict__ ad1,
                        const float* __restrict__ W2,
                        const float* __restrict__ as2, const float* __restrict__ ad2) {
    int i = blockIdx.x * blockDim.x + threadIdx.x;
    if (i < N_) g_deg[i] = 1;                      // self loop
    if (blockIdx.x == 0) {
        int t = threadIdx.x;
        if (t == 0) {
            int ok = 1;
            for (int k = 0; k < 32; k++)
                if (ei[2 * k + 1] != 0u) { ok = 0; break; }
            g_is64 = ok;
        }
        if (t < 64) {           // v1[k][h] = sum_c W1[k,h*64+c] * att1[h,c]
            int k = t >> 2, h = t & 3;
            float s = 0.f, d = 0.f;
            for (int c = 0; c < 64; c++) {
                float w = W1[k * 256 + h * 64 + c];
                s = fmaf(w, as1[h * 64 + c], s);
                d = fmaf(w, ad1[h * 64 + c], d);
            }
            g_vs1[k * 4 + h] = s;
            g_vd1[k * 4 + h] = d;
        }
        if (t >= 64 && t < 128) {   // v2[k] = sum_c W2[k,c] * att2[c]
            int k = t - 64;
            float s = 0.f, d = 0.f;
            for (int c = 0; c < 64; c++) {
                float w = W2[k * 64 + c];
                s = fmaf(w, as2[c], s);
                d = fmaf(w, ad2[c], d);
            }
            g_vs2[k] = s;
            g_vd2[k] = d;
        }
    }
}

__global__ void k_hist(const void* __restrict__ ei) {
    int e = blockIdx.x * blockDim.x + threadIdx.x;
    if (e >= E_) return;
    int2 sd = load_edge(ei, e);
    atomicAdd(&g_deg[sd.y], 1);
}

// ---------------- hierarchical exclusive scan ------------------------------
__global__ void k_scan1() {
    __shared__ int swarp[32];
    int t = threadIdx.x;
    int gid = blockIdx.x * SCAN_BLK + t;
    int lane = t & 31, wid = t >> 5;
    int v = (gid < N_) ? g_deg[gid] : 0;
    int x = v;
    #pragma unroll
    for (int o = 1; o < 32; o <<= 1) {
        int y = __shfl_up_sync(0xffffffffu, x, o);
        if (lane >= o) x += y;
    }
    if (lane == 31) swarp[wid] = x;
    __syncthreads();
    if (wid == 0) {
        int y = swarp[lane];
        #pragma unroll
        for (int o = 1; o < 32; o <<= 1) {
            int z = __shfl_up_sync(0xffffffffu, y, o);
            if (lane >= o) y += z;
        }
        swarp[lane] = y;
    }
    __syncthreads();
    int woff = (wid > 0) ? swarp[wid - 1] : 0;
    if (gid < N_) g_rp[gid] = woff + x - v;
    if (t == SCAN_BLK - 1) g_bsum[blockIdx.x] = woff + x;
}

__global__ void k_scan2() {
    int t = threadIdx.x;
    __shared__ int sm[64];
    int v = (t < SCAN_NB) ? g_bsum[t] : 0;
    sm[t] = v;
    __syncthreads();
    int x = v;
    #pragma unroll
    for (int o = 1; o < 64; o <<= 1) {
        int add = (t >= o) ? sm[t - o] : 0;
        __syncthreads();
        x += add; sm[t] = x;
        __syncthreads();
    }
    if (t < SCAN_NB) g_boff[t] = x - v;
    if (t == SCAN_NB - 1) g_boff[SCAN_NB] = x;
}

__global__ void k_scan3() {
    int gid = blockIdx.x * SCAN_BLK + threadIdx.x;
    if (gid < N_) {
        int r = g_rp[gid] + g_boff[blockIdx.x];
        g_rp[gid] = r;
        g_cursor[gid] = r;
    }
    if (gid == 0) g_rp[N_] = g_boff[SCAN_NB];
}

__global__ void k_scatter(const void* __restrict__ ei) {
    int e = blockIdx.x * blockDim.x + threadIdx.x;
    if (e >= ETOT) return;
    int s, d;
    if (e < E_) { int2 sd = load_edge(ei, e); s = sd.x; d = sd.y; }
    else        { s = d = e - E_; }
    int pos = atomicAdd(&g_cursor[d], 1);
    g_csr_src[pos] = s;
}

// ---------------- layer 1 GEMM: h1 = x @ W1 --------------------------------
__global__ void k_gemm1(const float* __restrict__ x, const float* __restrict__ W) {
    __shared__ float Ws[16 * 256];
    __shared__ float xs[16 * 16];
    int t = threadIdx.x;
    for (int i = t; i < 4096; i += 256) Ws[i] = W[i];
    int nb = blockIdx.x * 16;
    {
        int n = nb + (t >> 4);
        xs[t] = (n < N_) ? x[n * 16 + (t & 15)] : 0.f;
    }
    __syncthreads();
    #pragma unroll 4
    for (int i = 0; i < 16; i++) {
        int n = nb + i;
        if (n >= N_) break;
        float acc = 0.f;
        #pragma unroll
        for (int k = 0; k < 16; k++) acc = fmaf(xs[i * 16 + k], Ws[k * 256 + t], acc);
        g_h1[n * 256 + t] = acc;
    }
}

// ---------------- layer 1 logits: asrc1/adst1 = x @ v1 ---------------------
__global__ void k_logit1(const float* __restrict__ x) {
    __shared__ float vs[64], vd[64];
    if (threadIdx.x < 64) {
        vs[threadIdx.x] = g_vs1[threadIdx.x];
        vd[threadIdx.x] = g_vd1[threadIdx.x];
    }
    __syncthreads();
    int n = blockIdx.x * blockDim.x + threadIdx.x;
    if (n >= N_) return;
    const float4* xp = (const float4*)(x + n * 16);
    float4 xa = xp[0], xb = xp[1], xc = xp[2], xd = xp[3];
    float xv[16] = {xa.x, xa.y, xa.z, xa.w, xb.x, xb.y, xb.z, xb.w,
                    xc.x, xc.y, xc.z, xc.w, xd.x, xd.y, xd.z, xd.w};
    float s0 = 0, s1 = 0, s2 = 0, s3 = 0, d0 = 0, d1 = 0, d2 = 0, d3 = 0;
    #pragma unroll
    for (int k = 0; k < 16; k++) {
        float xk = xv[k];
        s0 = fmaf(xk, vs[k * 4 + 0], s0); d0 = fmaf(xk, vd[k * 4 + 0], d0);
        s1 = fmaf(xk, vs[k * 4 + 1], s1); d1 = fmaf(xk, vd[k * 4 + 1], d1);
        s2 = fmaf(xk, vs[k * 4 + 2], s2); d2 = fmaf(xk, vd[k * 4 + 2], d2);
        s3 = fmaf(xk, vs[k * 4 + 3], s3); d3 = fmaf(xk, vd[k * 4 + 3], d3);
    }
    *(float4*)&g_asrc1[n * 4] = make_float4(s0, s1, s2, s3);
    *(float4*)&g_adst1[n * 4] = make_float4(d0, d1, d2, d3);
}

// ---------------- layer 2 GEMM: h2 = x2 @ W2 -------------------------------
__global__ void k_gemm2(const float* __restrict__ W) {
    __shared__ float Ws[64 * 64];
    __shared__ float xs[16 * 65];
    int t = threadIdx.x;
    int col = t & 63;
    int g = t >> 6;
    for (int i = t; i < 4096; i += 256) Ws[i] = W[i];
    int nb = blockIdx.x * 16;
    for (int i = t; i < 1024; i += 256) {
        int n = nb + (i >> 6);
        xs[(i >> 6) * 65 + (i & 63)] = (n < N_) ? g_x2[n * 64 + (i & 63)] : 0.f;
    }
    __syncthreads();
    for (int it = 0; it < 4; it++) {
        int i = it * 4 + g;
        int n = nb + i;
        float acc = 0.f;
        #pragma unroll
        for (int k = 0; k < 64; k++) acc = fmaf(xs[i * 65 + k], Ws[k * 64 + col], acc);
        if (n < N_) g_h2[n * 64 + col] = acc;
    }
}

// ---------------- layer 1 fused softmax-aggregate (warp per dst) -----------
// No max-subtraction: logits are O(1) so exp() is fp32-safe; normalization
// by the denominator makes it algebraically identical to the stable form.
// Also emits layer-2 attention logits from the produced x2 row.
__global__ void k_agg1(const float* __restrict__ b1) {
    __shared__ int    sm_s[8 * 32];
    __shared__ float4 sm_ex[8 * 32];
    int lane = threadIdx.x & 31;
    int w = threadIdx.x >> 5;
    int d = blockIdx.x * 8 + w;
    if (d >= N_) return;
    int rsb = g_rp[d];
    int deg = g_rp[d + 1] - rsb;
    float4 adst = *(const float4*)&g_adst1[d * 4];
    int head = lane >> 3;

    float4 den = make_float4(0.f, 0.f, 0.f, 0.f);
    float4 a0 = make_float4(0.f, 0.f, 0.f, 0.f);
    float4 a1 = make_float4(0.f, 0.f, 0.f, 0.f);

    if (deg <= 32) {
        // ---- fast path: one gather, exp directly ----
        int s = -1;
        float4 ex = make_float4(0.f, 0.f, 0.f, 0.f);
        if (lane < deg) {
            s = g_csr_src[rsb + lane];
            float4 a = *(const float4*)&g_asrc1[s * 4];
            ex = make_float4(__expf(lrelu(a.x + adst.x)), __expf(lrelu(a.y + adst.y)),
                             __expf(lrelu(a.z + adst.z)), __expf(lrelu(a.w + adst.w)));
            den = ex;
        }
        sm_s[w * 32 + lane] = s;
        sm_ex[w * 32 + lane] = ex;
        __syncwarp();
        const float* exb = (const float*)&sm_ex[w * 32];
        int j = 0;
        for (; j + 1 < deg; j += 2) {
            int sj0 = sm_s[w * 32 + j],     sj1 = sm_s[w * 32 + j + 1];
            float e0 = exb[j * 4 + head],   e1 = exb[(j + 1) * 4 + head];
            const float4* p0 = (const float4*)&g_h1[sj0 * 256 + lane * 8];
            const float4* p1 = (const float4*)&g_h1[sj1 * 256 + lane * 8];
            float4 u0 = p0[0], u1 = p0[1], v0 = p1[0], v1 = p1[1];
            a0.x = fmaf(e0, u0.x, a0.x); a0.y = fmaf(e0, u0.y, a0.y);
            a0.z = fmaf(e0, u0.z, a0.z); a0.w = fmaf(e0, u0.w, a0.w);
            a1.x = fmaf(e0, u1.x, a1.x); a1.y = fmaf(e0, u1.y, a1.y);
            a1.z = fmaf(e0, u1.z, a1.z); a1.w = fmaf(e0, u1.w, a1.w);
            a0.x = fmaf(e1, v0.x, a0.x); a0.y = fmaf(e1, v0.y, a0.y);
            a0.z = fmaf(e1, v0.z, a0.z); a0.w = fmaf(e1, v0.w, a0.w);
            a1.x = fmaf(e1, v1.x, a1.x); a1.y = fmaf(e1, v1.y, a1.y);
            a1.z = fmaf(e1, v1.z, a1.z); a1.w = fmaf(e1, v1.w, a1.w);
        }
        if (j < deg) {
            int sj = sm_s[w * 32 + j];
            float e0 = exb[j * 4 + head];
            const float4* p0 = (const float4*)&g_h1[sj * 256 + lane * 8];
            float4 u0 = p0[0], u1 = p0[1];
            a0.x = fmaf(e0, u0.x, a0.x); a0.y = fmaf(e0, u0.y, a0.y);
            a0.z = fmaf(e0, u0.z, a0.z); a0.w = fmaf(e0, u0.w, a0.w);
            a1.x = fmaf(e0, u1.x, a1.x); a1.y = fmaf(e0, u1.y, a1.y);
            a1.z = fmaf(e0, u1.z, a1.z); a1.w = fmaf(e0, u1.w, a1.w);
        }
    } else {
        // ---- generic path: single pass, no max ----
        for (int base = 0; base < deg; base += 32) {
            int i = base + lane;
            int s = -1;
            float4 ex = make_float4(0.f, 0.f, 0.f, 0.f);
            if (i < deg) {
                s = g_csr_src[rsb + i];
                float4 a = *(const float4*)&g_asrc1[s * 4];
                ex.x = __expf(lrelu(a.x + adst.x));
                ex.y = __expf(lrelu(a.y + adst.y));
                ex.z = __expf(lrelu(a.z + adst.z));
                ex.w = __expf(lrelu(a.w + adst.w));
                den.x += ex.x; den.y += ex.y; den.z += ex.z; den.w += ex.w;
            }
            sm_s[w * 32 + lane] = s;
            sm_ex[w * 32 + lane] = ex;
            __syncwarp();
            int cnt = min(32, deg - base);
            const float* exb = (const float*)&sm_ex[w * 32];
            for (int j = 0; j < cnt; j++) {
                int sj = sm_s[w * 32 + j];
                float exj = exb[j * 4 + head];
                const float4* hp = (const float4*)&g_h1[sj * 256 + lane * 8];
                float4 v0 = hp[0], v1 = hp[1];
                a0.x = fmaf(exj, v0.x, a0.x); a0.y = fmaf(exj, v0.y, a0.y);
                a0.z = fmaf(exj, v0.z, a0.z); a0.w = fmaf(exj, v0.w, a0.w);
                a1.x = fmaf(exj, v1.x, a1.x); a1.y = fmaf(exj, v1.y, a1.y);
                a1.z = fmaf(exj, v1.z, a1.z); a1.w = fmaf(exj, v1.w, a1.w);
            }
            __syncwarp();
        }
    }

    #pragma unroll
    for (int o = 16; o > 0; o >>= 1) {
        den.x += __shfl_xor_sync(0xffffffffu, den.x, o);
        den.y += __shfl_xor_sync(0xffffffffu, den.y, o);
        den.z += __shfl_xor_sync(0xffffffffu, den.z, o);
        den.w += __shfl_xor_sync(0xffffffffu, den.w, o);
    }
    float dh = (head == 0 ? den.x : head == 1 ? den.y : head == 2 ? den.z : den.w);
    float inv = 1.f / (dh + 1e-16f);
    a0.x *= inv; a0.y *= inv; a0.z *= inv; a0.w *= inv;
    a1.x *= inv; a1.y *= inv; a1.z *= inv; a1.w *= inv;
    #pragma unroll
    for (int o = 8; o <= 16; o <<= 1) {
        a0.x += __shfl_xor_sync(0xffffffffu, a0.x, o);
        a0.y += __shfl_xor_sync(0xffffffffu, a0.y, o);
        a0.z += __shfl_xor_sync(0xffffffffu, a0.z, o);
        a0.w += __shfl_xor_sync(0xffffffffu, a0.w, o);
        a1.x += __shfl_xor_sync(0xffffffffu, a1.x, o);
        a1.y += __shfl_xor_sync(0xffffffffu, a1.y, o);
        a1.z += __shfl_xor_sync(0xffffffffu, a1.z, o);
        a1.w += __shfl_xor_sync(0xffffffffu, a1.w, o);
    }
    if (lane < 8) {
        int c = lane * 8;
        float o0 = eluf(0.25f * a0.x + b1[c + 0]);
        float o1 = eluf(0.25f * a0.y + b1[c + 1]);
        float o2 = eluf(0.25f * a0.z + b1[c + 2]);
        float o3 = eluf(0.25f * a0.w + b1[c + 3]);
        float o4 = eluf(0.25f * a1.x + b1[c + 4]);
        float o5 = eluf(0.25f * a1.y + b1[c + 5]);
        float o6 = eluf(0.25f * a1.z + b1[c + 6]);
        float o7 = eluf(0.25f * a1.w + b1[c + 7]);
        float* op = &g_x2[d * 64 + c];
        op[0] = o0; op[1] = o1; op[2] = o2; op[3] = o3;
        op[4] = o4; op[5] = o5; op[6] = o6; op[7] = o7;
        // layer-2 attention logits fused: asrc2[d] = x2[d,:] @ vs2
        float ps = o0 * g_vs2[c + 0] + o1 * g_vs2[c + 1] + o2 * g_vs2[c + 2] + o3 * g_vs2[c + 3]
                 + o4 * g_vs2[c + 4] + o5 * g_vs2[c + 5] + o6 * g_vs2[c + 6] + o7 * g_vs2[c + 7];
        float pd = o0 * g_vd2[c + 0] + o1 * g_vd2[c + 1] + o2 * g_vd2[c + 2] + o3 * g_vd2[c + 3]
                 + o4 * g_vd2[c + 4] + o5 * g_vd2[c + 5] + o6 * g_vd2[c + 6] + o7 * g_vd2[c + 7];
        #pragma unroll
        for (int o = 4; o > 0; o >>= 1) {
            ps += __shfl_xor_sync(0x000000ffu, ps, o);
            pd += __shfl_xor_sync(0x000000ffu, pd, o);
        }
        if (lane == 0) { g_asrc2[d] = ps; g_adst2[d] = pd; }
    }
}

// ---------------- layer 2 fused softmax-aggregate (warp per dst) -----------
__global__ void k_agg2(const float* __restrict__ b2, float* __restrict__ out) {
    __shared__ int   sm_s[8 * 32];
    __shared__ float sm_ex[8 * 32];
    int lane = threadIdx.x & 31;
    int w = threadIdx.x >> 5;
    int d = blockIdx.x * 8 + w;
    if (d >= N_) return;
    int rsb = g_rp[d];
    int deg = g_rp[d + 1] - rsb;
    float adst = g_adst2[d];

    float den = 0.f;
    float2 acc = make_float2(0.f, 0.f);

    if (deg <= 32) {
        int s = -1;
        float ex = 0.f;
        if (lane < deg) {
            s = g_csr_src[rsb + lane];
            ex = __expf(lrelu(g_asrc2[s] + adst));
            den = ex;
        }
        sm_s[w * 32 + lane] = s;
        sm_ex[w * 32 + lane] = ex;
        __syncwarp();
        int j = 0;
        for (; j + 1 < deg; j += 2) {
            int sj0 = sm_s[w * 32 + j], sj1 = sm_s[w * 32 + j + 1];
            float e0 = sm_ex[w * 32 + j], e1 = sm_ex[w * 32 + j + 1];
            float2 u = *(const float2*)&g_h2[sj0 * 64 + lane * 2];
            float2 v = *(const float2*)&g_h2[sj1 * 64 + lane * 2];
            acc.x = fmaf(e0, u.x, acc.x); acc.y = fmaf(e0, u.y, acc.y);
            acc.x = fmaf(e1, v.x, acc.x); acc.y = fmaf(e1, v.y, acc.y);
        }
        if (j < deg) {
            int sj = sm_s[w * 32 + j];
            float e0 = sm_ex[w * 32 + j];
            float2 u = *(const float2*)&g_h2[sj * 64 + lane * 2];
            acc.x = fmaf(e0, u.x, acc.x); acc.y = fmaf(e0, u.y, acc.y);
        }
    } else {
        for (int base = 0; base < deg; base += 32) {
            int i = base + lane;
            int s = -1;
            float ex = 0.f;
            if (i < deg) {
                s = g_csr_src[rsb + i];
                ex = __expf(lrelu(g_asrc2[s] + adst));
                den += ex;
            }
            sm_s[w * 32 + lane] = s;
            sm_ex[w * 32 + lane] = ex;
            __syncwarp();
            int cnt = min(32, deg - base);
            for (int j = 0; j < cnt; j++) {
                int sj = sm_s[w * 32 + j];
                float exj = sm_ex[w * 32 + j];
                float2 v = *(const float2*)&g_h2[sj * 64 + lane * 2];
                acc.x = fmaf(exj, v.x, acc.x);
                acc.y = fmaf(exj, v.y, acc.y);
            }
            __syncwarp();
        }
    }
    #pragma unroll
    for (int o = 16; o > 0; o >>= 1)
        den += __shfl_xor_sync(0xffffffffu, den, o);
    float inv = 1.f / (den + 1e-16f);
    int c = lane * 2;
    out[d * 64 + c + 0] = eluf(acc.x * inv + b2[c + 0]);
    out[d * 64 + c + 1] = eluf(acc.y * inv + b2[c + 1]);
}

// ---------------- launch ----------------------------------------------------
extern "C" void kernel_launch(void* const* d_in, const int* in_sizes, int n_in,
                              void* d_out, int out_size) {
    const float* x   = (const float*)d_in[0];
    const void*  ei  = d_in[1];
    const float* W1  = (const float*)d_in[2];
    const float* as1 = (const float*)d_in[3];
    const float* ad1 = (const float*)d_in[4];
    const float* b1  = (const float*)d_in[5];
    const float* W2  = (const float*)d_in[6];
    const float* as2 = (const float*)d_in[7];
    const float* ad2 = (const float*)d_in[8];
    const float* b2  = (const float*)d_in[9];
    float* out = (float*)d_out;

    k_setup<<<(N_ + 255) / 256, 256>>>((const unsigned int*)ei, W1, as1, ad1, W2, as2, ad2);
    k_hist<<<(E_ + 255) / 256, 256>>>(ei);
    k_scan1<<<SCAN_NB, SCAN_BLK>>>();
    k_scan2<<<1, 64>>>();
    k_scan3<<<SCAN_NB, SCAN_BLK>>>();
    k_scatter<<<(ETOT + 255) / 256, 256>>>(ei);

    k_gemm1<<<(N_ + 15) / 16, 256>>>(x, W1);
    k_logit1<<<(N_ + 255) / 256, 256>>>(x);
    k_agg1<<<(N_ + 7) / 8, 256>>>(b1);

    k_gemm2<<<(N_ + 15) / 16, 256>>>(W2);
    k_agg2<<<(N_ + 7) / 8, 256>>>(b2, out);
}